// round 6
// baseline (speedup 1.0000x reference)
#include <cuda_runtime.h>
#include <cuda_pipeline.h>

// InvertAffine: (B, 3, 4) fp32 affine shift matrices.
// inverse top-3-rows = [R, -R t], R = (I3+A)^-1 via closed-form 3x3 adjugate.
//
// Round-6: persistent blocks + cp.async double-buffered pipeline.
// Each block grid-strides over 256-matrix tiles; tile i+1 is prefetched via
// cp.async (LDGSTS, gmem->smem) while tile i is computed and stored, so the
// per-SM load stream never drains during store phases (fixes the barrier-
// quantized burstiness that pinned R2/R5 at ~76% DRAM).

constexpr int TILE = 256;         // matrices per tile
constexpr int TF4  = TILE * 3;    // float4 per tile (768 = 12 KB)

__device__ __forceinline__ void invert3(const float4 a0, const float4 a1, const float4 a2,
                                        float4& q0, float4& q1, float4& q2)
{
    // M = I3 + A, t = last column
    const float m00 = a0.x + 1.0f, m01 = a0.y,        m02 = a0.z,        t0 = a0.w;
    const float m10 = a1.x,        m11 = a1.y + 1.0f, m12 = a1.z,        t1 = a1.w;
    const float m20 = a2.x,        m21 = a2.y,        m22 = a2.z + 1.0f, t2 = a2.w;

    const float c00 = m11 * m22 - m12 * m21;
    const float c10 = m12 * m20 - m10 * m22;
    const float c20 = m10 * m21 - m11 * m20;
    const float det = m00 * c00 + m01 * c10 + m02 * c20;
    const float rdet = 1.0f / det;

    const float i00 = c00 * rdet;
    const float i01 = (m02 * m21 - m01 * m22) * rdet;
    const float i02 = (m01 * m12 - m02 * m11) * rdet;
    const float i10 = c10 * rdet;
    const float i11 = (m00 * m22 - m02 * m20) * rdet;
    const float i12 = (m02 * m10 - m00 * m12) * rdet;
    const float i20 = c20 * rdet;
    const float i21 = (m01 * m20 - m00 * m21) * rdet;
    const float i22 = (m00 * m11 - m01 * m10) * rdet;

    const float o0 = -(i00 * t0 + i01 * t1 + i02 * t2);
    const float o1 = -(i10 * t0 + i11 * t1 + i12 * t2);
    const float o2 = -(i20 * t0 + i21 * t1 + i22 * t2);

    q0 = make_float4(i00, i01, i02, o0);
    q1 = make_float4(i10, i11, i12, o1);
    q2 = make_float4(i20, i21, i22, o2);
}

__global__ void __launch_bounds__(256) invert_affine_kernel(
    const float4* __restrict__ in, float4* __restrict__ out, int b, int n_tiles)
{
    __shared__ float4 s_in[2][TF4];   // 24 KB double-buffered input
    __shared__ float4 s_out[TF4];     // 12 KB output staging

    const int t = threadIdx.x;
    const int stride = gridDim.x;

    // ── prologue: prefetch first tile into buf 0
    {
        const int tile = blockIdx.x;
        if (tile < n_tiles) {
            const int nf4 = min(TILE, b - tile * TILE) * 3;
            const long long g = (long long)tile * TF4;
#pragma unroll
            for (int k = 0; k < 3; k++) {
                const int idx = t + k * 256;
                if (idx < nf4)
                    __pipeline_memcpy_async(&s_in[0][idx], &in[g + idx], 16);
            }
        }
    }
    __pipeline_commit();

    int buf = 0;
    for (int tile = blockIdx.x; tile < n_tiles; tile += stride, buf ^= 1) {
        // ── prefetch next tile into the other buffer
        const int next = tile + stride;
        if (next < n_tiles) {
            const int nf4n = min(TILE, b - next * TILE) * 3;
            const long long gn = (long long)next * TF4;
#pragma unroll
            for (int k = 0; k < 3; k++) {
                const int idx = t + k * 256;
                if (idx < nf4n)
                    __pipeline_memcpy_async(&s_in[buf ^ 1][idx], &in[gn + idx], 16);
            }
        }
        __pipeline_commit();

        // ── wait for current tile (≤1 group pending = next tile's prefetch)
        __pipeline_wait_prior(1);
        __syncthreads();

        const int nmat = min(TILE, b - tile * TILE);
        const int nf4 = nmat * 3;
        const long long g = (long long)tile * TF4;

        if (t < nmat) {
            float4 q0, q1, q2;
            invert3(s_in[buf][3 * t + 0], s_in[buf][3 * t + 1], s_in[buf][3 * t + 2],
                    q0, q1, q2);
            s_out[3 * t + 0] = q0;
            s_out[3 * t + 1] = q1;
            s_out[3 * t + 2] = q2;
        }
        __syncthreads();

        // ── coalesced store (next tile's cp.async still filling the other buf)
#pragma unroll
        for (int k = 0; k < 3; k++) {
            const int idx = t + k * 256;
            if (idx < nf4) out[g + idx] = s_out[idx];
        }
    }
}

extern "C" void kernel_launch(void* const* d_in, const int* in_sizes, int n_in,
                              void* d_out, int out_size)
{
    const float4* in = (const float4*)d_in[0];
    float4* out = (float4*)d_out;
    const int b = in_sizes[0] / 12;  // (B, 3, 4) fp32 -> 12 elements per matrix

    const int n_tiles = (b + TILE - 1) / TILE;
    // 36 KB smem/block -> 6 blocks/SM on 152 SMs; grid-stride tolerates any mismatch
    int blocks = 152 * 6;
    if (blocks > n_tiles) blocks = n_tiles;
    invert_affine_kernel<<<blocks, 256>>>(in, out, b, n_tiles);
}

// round 7
// speedup vs baseline: 1.1515x; 1.1515x over previous
#include <cuda_runtime.h>

// InvertAffine: (B, 3, 4) fp32 affine shift matrices.
// inverse top-3-rows = [R, -R t], R = (I3+A)^-1 via closed-form 3x3 adjugate.
//
// Round-7: R5 structure (512-matrix tile, separate in/out smem, 2 syncs,
// fully coalesced gmem traffic) but with 512 threads/block: 1 matrix/thread,
// 48 KB smem -> exactly 4 blocks/SM = 64 warps (100% warp occupancy), half
// the per-tile barrier/loop overhead. All evidence says we're at the ~6.1
// TB/s mixed-R/W HBM ceiling; this targets the residual non-DRAM overhead.

constexpr int TILE = 512;          // matrices per block
constexpr int TF4  = TILE * 3;     // 1536 float4 = 24 KB per buffer

__device__ __forceinline__ void invert3(const float4 a0, const float4 a1, const float4 a2,
                                        float4& q0, float4& q1, float4& q2)
{
    // M = I3 + A, t = last column
    const float m00 = a0.x + 1.0f, m01 = a0.y,        m02 = a0.z,        t0 = a0.w;
    const float m10 = a1.x,        m11 = a1.y + 1.0f, m12 = a1.z,        t1 = a1.w;
    const float m20 = a2.x,        m21 = a2.y,        m22 = a2.z + 1.0f, t2 = a2.w;

    const float c00 = m11 * m22 - m12 * m21;
    const float c10 = m12 * m20 - m10 * m22;
    const float c20 = m10 * m21 - m11 * m20;
    const float det = m00 * c00 + m01 * c10 + m02 * c20;
    const float rdet = 1.0f / det;

    const float i00 = c00 * rdet;
    const float i01 = (m02 * m21 - m01 * m22) * rdet;
    const float i02 = (m01 * m12 - m02 * m11) * rdet;
    const float i10 = c10 * rdet;
    const float i11 = (m00 * m22 - m02 * m20) * rdet;
    const float i12 = (m02 * m10 - m00 * m12) * rdet;
    const float i20 = c20 * rdet;
    const float i21 = (m01 * m20 - m00 * m21) * rdet;
    const float i22 = (m00 * m11 - m01 * m10) * rdet;

    const float o0 = -(i00 * t0 + i01 * t1 + i02 * t2);
    const float o1 = -(i10 * t0 + i11 * t1 + i12 * t2);
    const float o2 = -(i20 * t0 + i21 * t1 + i22 * t2);

    q0 = make_float4(i00, i01, i02, o0);
    q1 = make_float4(i10, i11, i12, o1);
    q2 = make_float4(i20, i21, i22, o2);
}

__global__ void __launch_bounds__(512, 4) invert_affine_kernel(
    const float4* __restrict__ in, float4* __restrict__ out, int b)
{
    __shared__ float4 s_in[TF4];    // 24 KB
    __shared__ float4 s_out[TF4];   // 24 KB (48 KB total -> 4 blocks/SM)

    const int t = threadIdx.x;
    const int mbase = blockIdx.x * TILE;
    const long long fbase = (long long)mbase * 3;
    const int nmat = min(TILE, b - mbase);
    const int nf4 = nmat * 3;

    // Coalesced gmem -> smem: 3 front-batched LDG.128 per thread
#pragma unroll
    for (int k = 0; k < 3; k++) {
        const int idx = t + k * 512;
        if (idx < nf4) s_in[idx] = in[fbase + idx];
    }
    __syncthreads();

    if (t < nmat) {
        float4 q0, q1, q2;
        invert3(s_in[3 * t + 0], s_in[3 * t + 1], s_in[3 * t + 2], q0, q1, q2);
        s_out[3 * t + 0] = q0;
        s_out[3 * t + 1] = q1;
        s_out[3 * t + 2] = q2;
    }
    __syncthreads();

    // Coalesced smem -> gmem: 3 STG.128 per thread
#pragma unroll
    for (int k = 0; k < 3; k++) {
        const int idx = t + k * 512;
        if (idx < nf4) out[fbase + idx] = s_out[idx];
    }
}

extern "C" void kernel_launch(void* const* d_in, const int* in_sizes, int n_in,
                              void* d_out, int out_size)
{
    const float4* in = (const float4*)d_in[0];
    float4* out = (float4*)d_out;
    const int b = in_sizes[0] / 12;  // (B, 3, 4) fp32 -> 12 elements per matrix

    const int blocks = (b + TILE - 1) / TILE;
    invert_affine_kernel<<<blocks, 512>>>(in, out, b);
}

// round 8
// speedup vs baseline: 1.1664x; 1.0129x over previous
#include <cuda_runtime.h>

// InvertAffine: (B, 3, 4) fp32 affine shift matrices.
// inverse top-3-rows = [R, -R t], R = (I3+A)^-1 via closed-form 3x3 adjugate.
//
// Round-8: R5 geometry (the measured best: 512-matrix tile, 256 threads,
// 2 matrices/thread, split in/out smem buffers, 2 syncs, fully coalesced
// gmem, no cache hints) specialized into a predicate-free full-tile fast
// path (B is a multiple of 512 here) + a generic tail kernel. Removes all
// 12 per-thread bounds checks so the 6 LDG.128 issue as an unbroken
// front-batched run. We are at the ~6.1 TB/s mixed-R/W HBM ceiling; this
// targets residual instruction overhead only.

constexpr int TILE = 512;        // matrices per block
constexpr int TF4  = TILE * 3;   // 1536 float4 = 24 KB per buffer

__device__ __forceinline__ void invert3(const float4 a0, const float4 a1, const float4 a2,
                                        float4& q0, float4& q1, float4& q2)
{
    // M = I3 + A, t = last column
    const float m00 = a0.x + 1.0f, m01 = a0.y,        m02 = a0.z,        t0 = a0.w;
    const float m10 = a1.x,        m11 = a1.y + 1.0f, m12 = a1.z,        t1 = a1.w;
    const float m20 = a2.x,        m21 = a2.y,        m22 = a2.z + 1.0f, t2 = a2.w;

    const float c00 = m11 * m22 - m12 * m21;
    const float c10 = m12 * m20 - m10 * m22;
    const float c20 = m10 * m21 - m11 * m20;
    const float det = m00 * c00 + m01 * c10 + m02 * c20;
    const float rdet = 1.0f / det;

    const float i00 = c00 * rdet;
    const float i01 = (m02 * m21 - m01 * m22) * rdet;
    const float i02 = (m01 * m12 - m02 * m11) * rdet;
    const float i10 = c10 * rdet;
    const float i11 = (m00 * m22 - m02 * m20) * rdet;
    const float i12 = (m02 * m10 - m00 * m12) * rdet;
    const float i20 = c20 * rdet;
    const float i21 = (m01 * m20 - m00 * m21) * rdet;
    const float i22 = (m00 * m11 - m01 * m10) * rdet;

    const float o0 = -(i00 * t0 + i01 * t1 + i02 * t2);
    const float o1 = -(i10 * t0 + i11 * t1 + i12 * t2);
    const float o2 = -(i20 * t0 + i21 * t1 + i22 * t2);

    q0 = make_float4(i00, i01, i02, o0);
    q1 = make_float4(i10, i11, i12, o1);
    q2 = make_float4(i20, i21, i22, o2);
}

// Fast path: every tile full, zero predicates.
__global__ void __launch_bounds__(256) invert_affine_full_kernel(
    const float4* __restrict__ in, float4* __restrict__ out)
{
    __shared__ float4 s_in[TF4];
    __shared__ float4 s_out[TF4];

    const int t = threadIdx.x;
    const long long fbase = (long long)blockIdx.x * TF4;

    // 6 unguarded, front-batched, fully coalesced LDG.128 per thread
#pragma unroll
    for (int k = 0; k < 6; k++)
        s_in[t + k * 256] = in[fbase + t + k * 256];
    __syncthreads();

#pragma unroll
    for (int m = 0; m < 2; m++) {
        const int mi = t + m * 256;
        float4 q0, q1, q2;
        invert3(s_in[3 * mi + 0], s_in[3 * mi + 1], s_in[3 * mi + 2], q0, q1, q2);
        s_out[3 * mi + 0] = q0;
        s_out[3 * mi + 1] = q1;
        s_out[3 * mi + 2] = q2;
    }
    __syncthreads();

#pragma unroll
    for (int k = 0; k < 6; k++)
        out[fbase + t + k * 256] = s_out[t + k * 256];
}

// Tail: handles a final partial tile starting at matrix `mbase`.
__global__ void __launch_bounds__(256) invert_affine_tail_kernel(
    const float4* __restrict__ in, float4* __restrict__ out, int mbase, int b)
{
    __shared__ float4 s_in[TF4];
    __shared__ float4 s_out[TF4];

    const int t = threadIdx.x;
    const long long fbase = (long long)mbase * 3;
    const int nmat = b - mbase;
    const int nf4 = nmat * 3;

#pragma unroll
    for (int k = 0; k < 6; k++) {
        const int idx = t + k * 256;
        if (idx < nf4) s_in[idx] = in[fbase + idx];
    }
    __syncthreads();

#pragma unroll
    for (int m = 0; m < 2; m++) {
        const int mi = t + m * 256;
        if (mi < nmat) {
            float4 q0, q1, q2;
            invert3(s_in[3 * mi + 0], s_in[3 * mi + 1], s_in[3 * mi + 2], q0, q1, q2);
            s_out[3 * mi + 0] = q0;
            s_out[3 * mi + 1] = q1;
            s_out[3 * mi + 2] = q2;
        }
    }
    __syncthreads();

#pragma unroll
    for (int k = 0; k < 6; k++) {
        const int idx = t + k * 256;
        if (idx < nf4) out[fbase + idx] = s_out[idx];
    }
}

extern "C" void kernel_launch(void* const* d_in, const int* in_sizes, int n_in,
                              void* d_out, int out_size)
{
    const float4* in = (const float4*)d_in[0];
    float4* out = (float4*)d_out;
    const int b = in_sizes[0] / 12;  // (B, 3, 4) fp32 -> 12 elements per matrix

    const int full_tiles = b / TILE;        // 8192 for B = 4,194,304
    const int rem = b - full_tiles * TILE;  // 0 here

    if (full_tiles > 0)
        invert_affine_full_kernel<<<full_tiles, 256>>>(in, out);
    if (rem > 0)
        invert_affine_tail_kernel<<<1, 256>>>(in, out, full_tiles * TILE, b);
}